// round 12
// baseline (speedup 1.0000x reference)
#include <cuda_runtime.h>

// Closed-form evaluation (Heisenberg pullback) of the 4-qubit circuit.
//   EV0 = cw2*cw0*c0 - sw2*s0*s2
//   EV1 = cw1*c1
//   EV2 = cw0*c0*c2
//   EV3 = cw3*cw0*c0*c2*c3 - sw3*s3
// cq = cos(pi xq), sq = sin(pi xq); cwk/swk = cos/sin(wk).
//
// Finest-granularity config: 2048 blocks x 128 threads, 1 sample/thread.
// 262144 samples over 148 SMs: 2048 blocks -> 14-vs-13 blocks/SM (7.7%
// imbalance) vs 33% at 512 blocks. Minimal dependence chain per thread.

#ifndef PI_F
#define PI_F 3.14159265358979323846f
#endif

__global__ void __launch_bounds__(128)
quanv_fine_kernel(const float4* __restrict__ x,
                  const float4* __restrict__ w4,
                  float4* __restrict__ out)
{
    int i = blockIdx.x * blockDim.x + threadIdx.x;

    float4 xv = x[i];
    float4 wv = __ldg(w4);   // 16B uniform broadcast

    // weight trig (6 MUFU, uniform across warp) — overlaps x-load latency
    float cw0 = __cosf(wv.x);
    float cw1 = __cosf(wv.y);
    float cw2, sw2, cw3, sw3;
    __sincosf(wv.z, &sw2, &cw2);
    __sincosf(wv.w, &sw3, &cw3);

    // embedding trig (7 MUFU)
    float c0, s0, c1, c2, s2, c3, s3;
    __sincosf(PI_F * xv.x, &s0, &c0);
    c1 = __cosf(PI_F * xv.y);
    __sincosf(PI_F * xv.z, &s2, &c2);
    __sincosf(PI_F * xv.w, &s3, &c3);

    float z0  = cw0 * c0;     // <Z0> after RX(w0)
    float z02 = z0 * c2;      // <Z0 Z2>

    float4 ev;
    ev.x = cw2 * z0 - sw2 * (s0 * s2);
    ev.y = cw1 * c1;
    ev.z = z02;
    ev.w = cw3 * (z02 * c3) - sw3 * s3;

    out[i] = ev;              // write-back: dies in L2 across replays
}

extern "C" void kernel_launch(void* const* d_in, const int* in_sizes, int n_in,
                              void* d_out, int out_size)
{
    const float4* x  = (const float4*)d_in[0];  // [B,4] f32 as float4
    const float4* w4 = (const float4*)d_in[1];  // [4] f32 as one float4
    float4* out = (float4*)d_out;               // [B,4] f32 as float4
    int B = in_sizes[0] / 4;                    // 262144 samples

    int threads = 128;
    int blocks = B / threads;                   // 2048, exact for this shape
    if (blocks * threads != B) blocks++;        // safety; B is a multiple of 128 here
    quanv_fine_kernel<<<blocks, threads>>>(x, w4, out);
}

// round 13
// speedup vs baseline: 1.0047x; 1.0047x over previous
#include <cuda_runtime.h>

// Closed-form evaluation (Heisenberg pullback) of the 4-qubit circuit.
//   EV0 = cw2*cw0*c0 - sw2*s0*s2
//   EV1 = cw1*c1
//   EV2 = cw0*c0*c2
//   EV3 = cw3*cw0*c0*c2*c3 - sw3*s3
// cq = cos(pi xq), sq = sin(pi xq); cwk/swk = cos/sin(wk).
//
// Best-measured shape (ITEMS=4, 128-thread blocks) with Blackwell 256-bit
// vector loads/stores (ld/st.global.v8.f32, sm_100a+): 2 LDG.256 + 2 STG.256
// per thread instead of 4 LDG.128 + 4 STG.128 — halves memory-instruction
// count and L1tex wavefront-queue entries per warp.

#ifndef PI_F
#define PI_F 3.14159265358979323846f
#endif

struct __align__(32) f8 { float4 a; float4 b; };   // two samples per unit

__device__ __forceinline__ f8 ldg256(const f8* p) {
    f8 v;
    asm volatile("ld.global.nc.v8.f32 {%0,%1,%2,%3,%4,%5,%6,%7}, [%8];"
        : "=f"(v.a.x), "=f"(v.a.y), "=f"(v.a.z), "=f"(v.a.w),
          "=f"(v.b.x), "=f"(v.b.y), "=f"(v.b.z), "=f"(v.b.w)
        : "l"(p));
    return v;
}

__device__ __forceinline__ void stg256(f8* p, const f8& v) {
    asm volatile("st.global.v8.f32 [%0], {%1,%2,%3,%4,%5,%6,%7,%8};"
        :: "l"(p),
           "f"(v.a.x), "f"(v.a.y), "f"(v.a.z), "f"(v.a.w),
           "f"(v.b.x), "f"(v.b.y), "f"(v.b.z), "f"(v.b.w)
        : "memory");
}

__device__ __forceinline__ float4 eval_sample(
    const float4& xv,
    float cw0, float cw1, float cw2, float sw2, float cw3, float sw3)
{
    float c0, s0, c1, c2, s2, c3, s3;
    __sincosf(PI_F * xv.x, &s0, &c0);
    c1 = __cosf(PI_F * xv.y);
    __sincosf(PI_F * xv.z, &s2, &c2);
    __sincosf(PI_F * xv.w, &s3, &c3);

    float z0  = cw0 * c0;     // <Z0> after RX(w0)
    float z02 = z0 * c2;      // <Z0 Z2>

    float4 ev;
    ev.x = cw2 * z0 - sw2 * (s0 * s2);
    ev.y = cw1 * c1;
    ev.z = z02;
    ev.w = cw3 * (z02 * c3) - sw3 * s3;
    return ev;
}

__global__ void __launch_bounds__(128)
quanv_v8_kernel(const f8* __restrict__ x,
                const float4* __restrict__ w4,
                f8* __restrict__ out,
                int U)   // U = total threads = number of f8 pairs handled per stream
{
    int t = blockIdx.x * blockDim.x + threadIdx.x;

    // ---- front-batched: two independent 32B loads in flight ----
    f8 p0 = ldg256(&x[t]);
    f8 p1 = ldg256(&x[t + U]);
    float4 wv = __ldg(w4);    // 16B uniform broadcast

    // ---- weight trig: 6 MUFU, amortized over 4 samples ----
    float cw0 = __cosf(wv.x);
    float cw1 = __cosf(wv.y);
    float cw2, sw2, cw3, sw3;
    __sincosf(wv.z, &sw2, &cw2);
    __sincosf(wv.w, &sw3, &cw3);

    f8 e0, e1;
    e0.a = eval_sample(p0.a, cw0, cw1, cw2, sw2, cw3, sw3);
    e0.b = eval_sample(p0.b, cw0, cw1, cw2, sw2, cw3, sw3);
    e1.a = eval_sample(p1.a, cw0, cw1, cw2, sw2, cw3, sw3);
    e1.b = eval_sample(p1.b, cw0, cw1, cw2, sw2, cw3, sw3);

    stg256(&out[t], e0);
    stg256(&out[t + U], e1);
}

extern "C" void kernel_launch(void* const* d_in, const int* in_sizes, int n_in,
                              void* d_out, int out_size)
{
    const f8*     x  = (const f8*)d_in[0];      // [B,4] f32 as f8 (2 samples/unit)
    const float4* w4 = (const float4*)d_in[1];  // [4] f32 as one float4
    f8* out = (f8*)d_out;                       // [B,4] f32 as f8
    int B = in_sizes[0] / 4;                    // 262144 samples
    int P = B / 2;                              // 131072 f8 units
    int U = P / 2;                              // 65536 threads, 2 f8 each

    int threads = 128;
    int blocks = U / threads;                   // 512, exact for this shape
    if (blocks * threads != U) blocks++;        // safety; exact for B=262144
    quanv_v8_kernel<<<blocks, threads>>>(x, w4, out, U);
}

// round 15
// speedup vs baseline: 1.0435x; 1.0386x over previous
#include <cuda_runtime.h>

// Closed-form evaluation (Heisenberg pullback) of the 4-qubit circuit.
//   EV0 = cw2*cw0*c0 - sw2*s0*s2
//   EV1 = cw1*c1
//   EV2 = cw0*c0*c2
//   EV3 = cw3*cw0*c0*c2*c3 - sw3*s3
// cq = cos(pi xq), sq = sin(pi xq); cwk/swk = cos/sin(wk).
//
// Best-measured configuration across the 11-bench sweep (6.624us):
// 4 samples per thread, 128-thread blocks, front-batched loads (MLP=4).
// The problem sits at a launch+one-wave-latency floor (~6.6us): no pipe
// exceeds 21%, DRAM ~10%, and all structural variants land within noise.

#ifndef PI_F
#define PI_F 3.14159265358979323846f
#endif

#define ITEMS 4

__global__ void __launch_bounds__(128)
quanv_closed4_kernel(const float4* __restrict__ x,
                     const float* __restrict__ w,
                     float4* __restrict__ out,
                     int T)   // T = total threads = B / ITEMS
{
    int t = blockIdx.x * blockDim.x + threadIdx.x;
    if (t >= T) return;

    // ---- front-batched loads: 4 independent 16B transactions in flight ----
    float4 a[ITEMS];
#pragma unroll
    for (int k = 0; k < ITEMS; k++)
        a[k] = x[t + k * T];

    // ---- weight trig, once per thread (uniform; amortized over 4 samples) ----
    float cw0 = __cosf(__ldg(&w[0]));
    float cw1 = __cosf(__ldg(&w[1]));
    float cw2, sw2, cw3, sw3;
    __sincosf(__ldg(&w[2]), &sw2, &cw2);
    __sincosf(__ldg(&w[3]), &sw3, &cw3);

    float4 ev[ITEMS];
#pragma unroll
    for (int k = 0; k < ITEMS; k++) {
        float c0, s0, c1, c2, s2, c3, s3;
        __sincosf(PI_F * a[k].x, &s0, &c0);
        c1 = __cosf(PI_F * a[k].y);
        __sincosf(PI_F * a[k].z, &s2, &c2);
        __sincosf(PI_F * a[k].w, &s3, &c3);

        float z0  = cw0 * c0;     // <Z0> after RX(w0)
        float z02 = z0 * c2;      // <Z0 Z2>

        ev[k].x = cw2 * z0 - sw2 * (s0 * s2);
        ev[k].y = cw1 * c1;
        ev[k].z = z02;
        ev[k].w = cw3 * (z02 * c3) - sw3 * s3;
    }

#pragma unroll
    for (int k = 0; k < ITEMS; k++)
        out[t + k * T] = ev[k];
}

extern "C" void kernel_launch(void* const* d_in, const int* in_sizes, int n_in,
                              void* d_out, int out_size)
{
    const float4* x = (const float4*)d_in[0];   // [B,4] f32 as float4
    const float*  w = (const float*)d_in[1];    // [4] f32
    float4* out = (float4*)d_out;               // [B,4] f32 as float4
    int B = in_sizes[0] / 4;          // number of samples (float4 rows)
    int T = B / ITEMS;                // 262144 / 4 = 65536 threads
    if (T * ITEMS != B) T = (B + ITEMS - 1) / ITEMS;  // (not hit for this shape)

    int threads = 128;
    int blocks = (T + threads - 1) / threads;   // 512 blocks
    quanv_closed4_kernel<<<blocks, threads>>>(x, w, out, T);
}